// round 17
// baseline (speedup 1.0000x reference)
#include <cuda_runtime.h>

// StatelessConvLIF: fused 3x3 SAME conv (fp32) + LIF scan over T=8.
// x: [8,16,64,64,64] fp32, W: [128,64,3,3] fp32, out spikes: [8,16,128,64,64] fp32.
//
// R17: occupancy round. NCO 8 -> 4 (2 co-pairs/thread) halves A/V register
// state so the kernel fits 84 regs -> __launch_bounds__(256,3) = 3 blocks/SM
// = 6 warps/SMSP (was 4). R16 showed fma pipe-busy already at its floor
// (~1105us) but issue=57% / fma=59.6% from stall coverage with only 4 warps.
// Grid z doubles (32 cout groups). Per-output tap accumulation order
// unchanged (cin asc, ky asc, kx asc, co-pair packing) -> rel_err must stay
// 7.0777e-4. Keeps the 3-stage cp.async ring with wait_group 1.

#define THREADS 256
#define CHUNK   4
#define XSTRIDE 36                      // 34 cols padded to 36
#define XBUF    (CHUNK * 34 * XSTRIDE)  // floats per stage = 4896
#define STAGES  3
#define NCO     4                       // couts per block (2 co-pairs)
#define NCP     (NCO / 2)
#define T_STEPS 8
#define BATCH   16
#define CIN     64
#define COUT    128
#define HW      64
#define NCHUNKS (T_STEPS * 16)          // 128
// weight smem: [cin][ky][cp][4] pairs (tap 3 = pad); 64*3*NCP*4 pairs * 8B
#define WS_PAIRS (CIN * 3 * NCP * 4)

typedef unsigned long long ull;

__device__ __forceinline__ ull pk2(float lo, float hi) {
    ull r; asm("mov.b64 %0, {%1, %2};" : "=l"(r) : "f"(lo), "f"(hi)); return r;
}
__device__ __forceinline__ void upk2(ull a, float& lo, float& hi) {
    asm("mov.b64 {%0, %1}, %2;" : "=f"(lo), "=f"(hi) : "l"(a));
}
__device__ __forceinline__ void ffma2(ull& d, ull a, ull b) {
    asm("fma.rn.f32x2 %0, %1, %2, %0;" : "+l"(d) : "l"(a), "l"(b));
}
__device__ __forceinline__ void cp4(unsigned dst, const float* src, unsigned sz) {
    asm volatile("cp.async.ca.shared.global [%0], [%1], 4, %2;"
                 :: "r"(dst), "l"(src), "r"(sz));
}
__device__ __forceinline__ void cp_commit() {
    asm volatile("cp.async.commit_group;");
}
__device__ __forceinline__ void cp_wait1() {
    asm volatile("cp.async.wait_group 1;");   // newest group may stay in flight
}

__global__ __launch_bounds__(THREADS, 3)
void convlif_kernel(const float* __restrict__ x,
                    const float* __restrict__ w,
                    float* __restrict__ out)
{
    extern __shared__ float smem[];
    // layout: xs[STAGES][XBUF] | ws[cin][ky][cp][4] co-pair weight pairs
    ull* ws = (ull*)(smem + STAGES * XBUF);

    const int tid  = threadIdx.x;
    const int lane = tid & 31;
    const int warp = tid >> 5;
    const int tx   = tid & 7;        // col-group: 4 pixels at w0 + 4*tx
    const int ty   = tid >> 3;       // row within tile: 0..31
    const int h0   = (blockIdx.x >> 1) * 32;
    const int w0   = (blockIdx.x & 1) * 32;
    const int b    = blockIdx.y;
    const int cg   = blockIdx.z;     // 32 groups of 4 couts

    // Weights -> smem as {w[2cp], w[2cp+1]} pairs, layout [cin][ky][cp][4].
    {
        const float* wg = w + (size_t)cg * NCO * CIN * 9;
        for (int i = tid; i < CIN * 3 * NCP * 3; i += THREADS) {  // 1152 entries
            int cin = i / (3 * NCP * 3);  int r  = i - cin * (3 * NCP * 3);
            int ky  = r / (NCP * 3);      int r2 = r - ky * (NCP * 3);
            int cp  = r2 / 3;             int tap = r2 - cp * 3;
            float we = wg[(2 * cp)     * CIN * 9 + cin * 9 + ky * 3 + tap];
            float wo = wg[(2 * cp + 1) * CIN * 9 + cin * 9 + ky * 3 + tap];
            ws[((cin * 3 + ky) * NCP + cp) * 4 + tap] = pk2(we, wo);
        }
    }

    // Loader geometry (division-free): warp covers channel c = warp>>1 and 17
    // rows starting at (warp&1)*17; lane covers col = lane (+ lanes 0/1: 32/33).
    const int lc    = warp >> 1;
    const int lrow0 = (warp & 1) * 17;
    const int gw_m  = w0 + lane - 1;
    const unsigned okw_m = ((unsigned)gw_m < HW) ? 4u : 0u;
    const int gwc_m = (gw_m < 0) ? 0 : (gw_m >= HW ? HW - 1 : gw_m);
    const int gw_t  = w0 + 32 + lane - 1;
    const unsigned okw_t = ((unsigned)gw_t < HW) ? 4u : 0u;
    const int gwc_t = (gw_t >= HW) ? HW - 1 : gw_t;

    unsigned smem_u32;
    {
        void* p = smem;
        asm("{ .reg .u64 t; cvta.to.shared.u64 t, %1; cvt.u32.u64 %0, t; }"
            : "=r"(smem_u32) : "l"(p));
    }

    // Prefetch chunk g into stage s.
    auto prefetch = [&](int g, int s) {
        if (g < NCHUNKS) {
            const int t  = g >> 4;
            const int ch = g & 15;
            const float* xb = x + (((size_t)t * BATCH + b) * CIN + ch * CHUNK + lc) * (HW * HW);
            unsigned dst0 = smem_u32 + (unsigned)(s * XBUF + lc * 34 * XSTRIDE) * 4u;
#pragma unroll 1
            for (int j = 0; j < 17; j++) {
                const int row = lrow0 + j;
                const int gh  = h0 + row - 1;
                const unsigned okh = ((unsigned)gh < HW) ? 4u : 0u;
                const int ghc = (gh < 0) ? 0 : (gh >= HW ? HW - 1 : gh);
                const float* srow = xb + ghc * HW;
                unsigned drow = dst0 + (unsigned)(row * XSTRIDE) * 4u;
                cp4(drow + (unsigned)lane * 4u, srow + gwc_m, okh & okw_m);
                if (lane < 2)
                    cp4(drow + (unsigned)(32 + lane) * 4u, srow + gwc_t, okh & okw_t);
            }
        }
        cp_commit();
    };

    // Prologue: chunks 0 and 1 into stages 0 and 1.
    prefetch(0, 0);
    prefetch(1, 1);

    // A[cp][px] = conv accumulator pair {o(px, 2cp), o(px, 2cp+1)}
    // V[cp][px] = membrane potential, same packing.
    ull A[NCP][4], V[NCP][4];
#pragma unroll
    for (int cp = 0; cp < NCP; cp++)
#pragma unroll
        for (int px = 0; px < 4; px++) { A[cp][px] = 0ull; V[cp][px] = 0ull; }

    int buf = 0;    // consumer stage for chunk g
    int nbuf = 2;   // producer stage for chunk g+2

#pragma unroll 1
    for (int g = 0; g < NCHUNKS; g++) {
        cp_wait1();            // group g complete (g+1 may stay in flight)
        __syncthreads();       // all threads see chunk g; stage nbuf free

        prefetch(g + 2, nbuf);
        nbuf = (nbuf == STAGES - 1) ? 0 : nbuf + 1;

        const float* xs = smem + buf * XBUF;
        const int cin0 = (g & 15) * CHUNK;

#pragma unroll 1
        for (int c = 0; c < CHUNK; c++) {
            const float* xr = xs + (c * 34 + ty) * XSTRIDE + tx * 4;
            const ull* wrow = ws + (size_t)(cin0 + c) * (3 * NCP * 4); // [ky][cp][4]
#pragma unroll
            for (int ky = 0; ky < 3; ky++) {
                float4 a4 = *(const float4*)(xr + ky * XSTRIDE);
                float2 b2 = *(const float2*)(xr + ky * XSTRIDE + 4);
                ull S0 = pk2(a4.x, a4.x);
                ull S1 = pk2(a4.y, a4.y);
                ull S2 = pk2(a4.z, a4.z);
                ull S3 = pk2(a4.w, a4.w);
                ull S4 = pk2(b2.x, b2.x);
                ull S5 = pk2(b2.y, b2.y);
                const ull* wk = wrow + ky * (NCP * 4);
#pragma unroll
                for (int cp = 0; cp < NCP; cp++) {
                    ulonglong2 w01 = *(const ulonglong2*)(wk + cp * 4); // taps 0,1
                    ull w2 = wk[cp * 4 + 2];                            // tap 2
                    // kx = 0
                    ffma2(A[cp][0], S0, w01.x);
                    ffma2(A[cp][1], S1, w01.x);
                    ffma2(A[cp][2], S2, w01.x);
                    ffma2(A[cp][3], S3, w01.x);
                    // kx = 1
                    ffma2(A[cp][0], S1, w01.y);
                    ffma2(A[cp][1], S2, w01.y);
                    ffma2(A[cp][2], S3, w01.y);
                    ffma2(A[cp][3], S4, w01.y);
                    // kx = 2
                    ffma2(A[cp][0], S2, w2);
                    ffma2(A[cp][1], S3, w2);
                    ffma2(A[cp][2], S4, w2);
                    ffma2(A[cp][3], S5, w2);
                }
            }
        }

        if ((g & 15) == 15) {
            const int t = g >> 4;
            // LIF update + spike store (reference op order: v += (z - v)/2).
#pragma unroll
            for (int cp = 0; cp < NCP; cp++) {
                float ze[4], zo[4], ue[4], uo[4];
#pragma unroll
                for (int px = 0; px < 4; px++) {
                    upk2(A[cp][px], ze[px], zo[px]);
                    upk2(V[cp][px], ue[px], uo[px]);
                }
                float4 se, so;
                ue[0] += (ze[0] - ue[0]) * 0.5f;
                ue[1] += (ze[1] - ue[1]) * 0.5f;
                ue[2] += (ze[2] - ue[2]) * 0.5f;
                ue[3] += (ze[3] - ue[3]) * 0.5f;
                uo[0] += (zo[0] - uo[0]) * 0.5f;
                uo[1] += (zo[1] - uo[1]) * 0.5f;
                uo[2] += (zo[2] - uo[2]) * 0.5f;
                uo[3] += (zo[3] - uo[3]) * 0.5f;
                se.x = (ue[0] >= 1.0f) ? 1.f : 0.f;  if (ue[0] >= 1.0f) ue[0] = 0.f;
                se.y = (ue[1] >= 1.0f) ? 1.f : 0.f;  if (ue[1] >= 1.0f) ue[1] = 0.f;
                se.z = (ue[2] >= 1.0f) ? 1.f : 0.f;  if (ue[2] >= 1.0f) ue[2] = 0.f;
                se.w = (ue[3] >= 1.0f) ? 1.f : 0.f;  if (ue[3] >= 1.0f) ue[3] = 0.f;
                so.x = (uo[0] >= 1.0f) ? 1.f : 0.f;  if (uo[0] >= 1.0f) uo[0] = 0.f;
                so.y = (uo[1] >= 1.0f) ? 1.f : 0.f;  if (uo[1] >= 1.0f) uo[1] = 0.f;
                so.z = (uo[2] >= 1.0f) ? 1.f : 0.f;  if (uo[2] >= 1.0f) uo[2] = 0.f;
                so.w = (uo[3] >= 1.0f) ? 1.f : 0.f;  if (uo[3] >= 1.0f) uo[3] = 0.f;
#pragma unroll
                for (int px = 0; px < 4; px++) {
                    V[cp][px] = pk2(ue[px], uo[px]);
                    A[cp][px] = 0ull;
                }
                const size_t base = (((size_t)t * BATCH + b) * COUT + cg * NCO + 2 * cp);
                size_t oe = ((base)     * HW + (h0 + ty)) * HW + (w0 + tx * 4);
                size_t oo = ((base + 1) * HW + (h0 + ty)) * HW + (w0 + tx * 4);
                *(float4*)(out + oe) = se;
                *(float4*)(out + oo) = so;
            }
        }

        buf = (buf == STAGES - 1) ? 0 : buf + 1;
    }
}

extern "C" void kernel_launch(void* const* d_in, const int* in_sizes, int n_in,
                              void* d_out, int out_size)
{
    const float* x = (const float*)d_in[0];
    const float* w = (const float*)d_in[1];
    float* out     = (float*)d_out;

    const int smem_bytes = STAGES * XBUF * 4   // x ring: 58,752 B
                         + WS_PAIRS * 8;       // weights: 12,288 B -> 71,040 B
    cudaFuncSetAttribute(convlif_kernel,
                         cudaFuncAttributeMaxDynamicSharedMemorySize, smem_bytes);

    dim3 grid(4 /* 2x2 spatial tiles */, BATCH, COUT / NCO);   // z = 32
    convlif_kernel<<<grid, THREADS, smem_bytes>>>(x, w, out);
}